// round 17
// baseline (speedup 1.0000x reference)
#include <cuda_runtime.h>
#include <cuda_bf16.h>
#include <cstdint>

// AtomTypeLinear: out[n,:] = x[n,:] @ M[type[n]] + b[type[n]]
// N=100000, IN=OUT=64, NUM_TYPES=64, fp32.
//
// k_sort: barrier-free counting sort into fixed-capacity per-type segments
//         + W transpose/convert to tf32; fires PDL trigger when done.
// k_gemm (PDL-gated): per-type GEMM, mma.m16n8k8 tf32.
//         NEW: 4 half-tile stages (32 rows each) -> 3 cp.async groups in
//         flight at constant occupancy (4 blocks/SM, 64 regs, 51KB smem).
//         Warp layout 2m x 4n (warp tile m16n16). cp.async.cg, quad-k
//         permutation -> LDS.128, XOR swizzle, idx preloaded to smem.

#define NUM_TYPES 64
#define CAP       4096    // per-type capacity (mean 1562, >60 sigma)
#define NB        256     // sort blocks
#define SLOTS     9       // gemm tile-slots per type (576 blocks, single wave)
#define MAXT      8       // max tiles per slot

__device__ int g_count[NUM_TYPES];        // zero-init; reset by k_gemm
__device__ int g_done[NUM_TYPES];         // zero-init; self-resetting
__device__ int g_perm[NUM_TYPES * CAP];
__device__ uint32_t g_wtf[NUM_TYPES * 4096];   // tf32 bits, [type][n][k]

// ---------------------------------------------------------------------------
__device__ __forceinline__ uint32_t f2tf32(float f) {
    uint32_t r;
    asm("cvt.rna.tf32.f32 %0, %1;" : "=r"(r) : "f"(f));
    return r;
}

__device__ __forceinline__ void mma_tf32(float* c,
                                         uint32_t a0, uint32_t a1,
                                         uint32_t a2, uint32_t a3,
                                         uint32_t b0, uint32_t b1) {
    asm volatile(
        "mma.sync.aligned.m16n8k8.row.col.f32.tf32.tf32.f32 "
        "{%0,%1,%2,%3}, {%4,%5,%6,%7}, {%8,%9}, {%0,%1,%2,%3};"
        : "+f"(c[0]), "+f"(c[1]), "+f"(c[2]), "+f"(c[3])
        : "r"(a0), "r"(a1), "r"(a2), "r"(a3), "r"(b0), "r"(b1));
}

// L1-bypassing 16B async copy (L2 -> smem).
__device__ __forceinline__ void cp_async16(uint32_t dst, const void* src) {
    asm volatile("cp.async.cg.shared.global [%0], [%1], 16;" :: "r"(dst), "l"(src));
}
__device__ __forceinline__ void cp_commit() {
    asm volatile("cp.async.commit_group;");
}
template <int N>
__device__ __forceinline__ void cp_wait() {
    asm volatile("cp.async.wait_group %0;" :: "n"(N));
}

// ---------------------------------------------------------------------------
// Kernel 1: barrier-free counting sort + W transpose/convert (R16).
// ---------------------------------------------------------------------------
__global__ void __launch_bounds__(256)
k_sort(const void* __restrict__ types, const float* __restrict__ Wm, int n) {
    __shared__ int sh[NUM_TYPES];
    __shared__ int s_cursor[NUM_TYPES];
    __shared__ int s_is64;
    __shared__ float sW[16][65];

    const int tid = threadIdx.x;
    const int b   = blockIdx.x;

    if (tid < NUM_TYPES) sh[tid] = 0;
    if (tid == 0) s_is64 = 1;
    __syncthreads();
    // int64 (LE) => every odd 32-bit word is 0 (values < 64).
    if (tid < 64) {
        int idx = 2 * tid + 1;
        if (idx < n && ((const int*)types)[idx] != 0) s_is64 = 0;
    }
    __syncthreads();
    const int is64 = s_is64;

    const int chunk = (((n + NB - 1) / NB) + 3) & ~3;
    const int lo = b * chunk;
    const int hi = min(n, lo + chunk);
    const int m  = hi - lo;

    // --- histogram ---
    if (m > 0) {
        if (is64) {
            const int4* p = (const int4*)((const long long*)types + lo);
            for (int e = tid * 2; e < m; e += 512) {
                if (e + 1 < m) {
                    int4 v = p[e >> 1];
                    atomicAdd(&sh[v.x & 63], 1);
                    atomicAdd(&sh[v.z & 63], 1);
                } else {
                    int t = (int)((const long long*)types)[lo + e];
                    atomicAdd(&sh[t & 63], 1);
                }
            }
        } else {
            const int4* p = (const int4*)((const int*)types + lo);
            for (int e = tid * 4; e < m; e += 1024) {
                if (e + 3 < m) {
                    int4 v = p[e >> 2];
                    atomicAdd(&sh[v.x & 63], 1);
                    atomicAdd(&sh[v.y & 63], 1);
                    atomicAdd(&sh[v.z & 63], 1);
                    atomicAdd(&sh[v.w & 63], 1);
                } else {
                    for (int j = e; j < m; j++)
                        atomicAdd(&sh[((const int*)types)[lo + j] & 63], 1);
                }
            }
        }
    }
    __syncthreads();

    if (tid < NUM_TYPES)
        s_cursor[tid] = atomicAdd(&g_count[tid], sh[tid]);

    // --- W transpose + tf32 convert: 16 k-rows per block ---
    {
        const int ty = b >> 2;
        const int k0 = (b & 3) * 16;
        const float* Wt = Wm + ty * 4096 + k0 * 64;   // [16 k-rows][64 n]
        for (int idx = tid; idx < 1024; idx += 256)
            sW[idx >> 6][idx & 63] = Wt[idx];          // coalesced read
        __syncthreads();
        for (int idx = tid; idx < 1024; idx += 256) {
            int nn = idx >> 4, kk = idx & 15;
            g_wtf[ty * 4096 + nn * 64 + k0 + kk] = f2tf32(sW[kk][nn]);
        }
    }
    __syncthreads();   // s_cursor ready for all threads

    // --- scatter into fixed-capacity segments ---
    if (m > 0) {
        if (is64) {
            const int4* p = (const int4*)((const long long*)types + lo);
            for (int e = tid * 2; e < m; e += 512) {
                if (e + 1 < m) {
                    int4 v = p[e >> 1];
                    int t0 = v.x & 63, t1 = v.z & 63;
                    int p0 = atomicAdd(&s_cursor[t0], 1);
                    int p1 = atomicAdd(&s_cursor[t1], 1);
                    if (p0 < CAP) g_perm[t0 * CAP + p0] = lo + e;
                    if (p1 < CAP) g_perm[t1 * CAP + p1] = lo + e + 1;
                } else {
                    int t = (int)((const long long*)types)[lo + e] & 63;
                    int p0 = atomicAdd(&s_cursor[t], 1);
                    if (p0 < CAP) g_perm[t * CAP + p0] = lo + e;
                }
            }
        } else {
            const int4* p = (const int4*)((const int*)types + lo);
            for (int e = tid * 4; e < m; e += 1024) {
                if (e + 3 < m) {
                    int4 v = p[e >> 2];
                    int t0 = v.x & 63, t1 = v.y & 63;
                    int t2 = v.z & 63, t3 = v.w & 63;
                    int p0 = atomicAdd(&s_cursor[t0], 1);
                    int p1 = atomicAdd(&s_cursor[t1], 1);
                    int p2 = atomicAdd(&s_cursor[t2], 1);
                    int p3 = atomicAdd(&s_cursor[t3], 1);
                    if (p0 < CAP) g_perm[t0 * CAP + p0] = lo + e;
                    if (p1 < CAP) g_perm[t1 * CAP + p1] = lo + e + 1;
                    if (p2 < CAP) g_perm[t2 * CAP + p2] = lo + e + 2;
                    if (p3 < CAP) g_perm[t3 * CAP + p3] = lo + e + 3;
                } else {
                    for (int j = e; j < m; j++) {
                        int t = ((const int*)types)[lo + j] & 63;
                        int p0 = atomicAdd(&s_cursor[t], 1);
                        if (p0 < CAP) g_perm[t * CAP + p0] = lo + j;
                    }
                }
            }
        }
    }

    // All of this block's global writes are done -> allow dependent launch.
    cudaTriggerProgrammaticLaunchCompletion();
}

// ---------------------------------------------------------------------------
// Kernel 2: GEMM with 4 half-tile stages (32 rows each), PDL-gated.
// Warp layout 2m x 4n: warp (wm, wn) computes rows [wm*16, wm*16+16) of the
// 32-row half-stage, cols [wn*16, wn*16+16). One cp.async group per
// half-stage; wait_group<2> -> 3 half-stages (24KB) in flight.
// ---------------------------------------------------------------------------
#define DSMEM_FLOATS (4096 + 64 + MAXT * 64 + 4 * 2048)
#define DSMEM_BYTES  (DSMEM_FLOATS * 4)

__global__ void __launch_bounds__(256, 4)
k_gemm(const float* __restrict__ x, const float* __restrict__ bias,
       float* __restrict__ out) {
    extern __shared__ float dsm[];
    float* Ws      = dsm;                     // [64 n][64 k] quad, swizzled
    float* bsm     = Ws + 4096;               // [64]
    int*   idx_all = (int*)(bsm + 64);        // [MAXT][64]
    float* As      = (float*)(idx_all + MAXT * 64);  // [4][32][64] swizzled

    // Wait for k_sort's writes (g_count/g_perm/g_wtf) to be visible.
    cudaGridDependencySynchronize();

    const int type  = blockIdx.y;
    const int count = min(g_count[type], CAP);
    const int ntiles = (count + 63) >> 6;
    const int tid  = threadIdx.x;
    const int slot = blockIdx.x;

    if (slot < ntiles) {
        const int segbase = type * CAP;
        // local tile count for this slot
        const int nloc = (ntiles - 1 - slot) / SLOTS + 1;
        const int L    = 2 * nloc;            // half-stages to process

        const int c   = tid & 15;    // 16B chunk within a row
        const int j0h = tid >> 4;    // row base within 32-row half (0..15)

        // --- W + bias cp.asyncs (independent of indices) ---
        {
            const uint32_t* Wsrc = g_wtf + type * 4096;
#pragma unroll
            for (int q = 0; q < 4; q++) {
                int idx = q * 256 + tid;            // 1024 chunks of 16B
                int row = idx >> 4, cc = idx & 15;
                int pc = cc ^ ((row & 1) << 2);
                uint32_t d = (uint32_t)__cvta_generic_to_shared(
                    Ws + row * 64 + pc * 4);
                cp_async16(d, Wsrc + row * 64 + cc * 4);
            }
            if (tid < 16) {
                uint32_t d = (uint32_t)__cvta_generic_to_shared(bsm + tid * 4);
                cp_async16(d, bias + type * 64 + tid * 4);
            }
        }

        // --- preload ALL of this block's tile indices (coalesced burst) ---
#pragma unroll
        for (int pass = 0; pass < 2; pass++) {
            int ti  = pass * 4 + (tid >> 6);
            int row = tid & 63;
            int t   = slot + ti * SLOTS;
            int r   = t * 64 + row;
            idx_all[ti * 64 + row] =
                (t < ntiles && r < count) ? __ldg(&g_perm[segbase + r]) : -1;
        }
        __syncthreads();   // idx_all visible before anyone reads it

        // Load half-stage hi (local) into stage buffer s. Rows j0h, j0h+16.
#define LOAD_HALF(s, hi)                                                      \
    do {                                                                      \
        float* dstb = As + (s) * 2048;                                        \
        int lt   = (hi) >> 1;                                                 \
        int hoff = ((hi) & 1) * 32;                                           \
        _Pragma("unroll")                                                     \
        for (int q = 0; q < 2; q++) {                                         \
            int j = j0h + q * 16;                                             \
            int idx = idx_all[lt * 64 + hoff + j];                            \
            int use = idx >= 0 ? idx : 0;                                     \
            int pc = c ^ ((j & 1) << 2);                                      \
            uint32_t d = (uint32_t)__cvta_generic_to_shared(                  \
                dstb + j * 64 + pc * 4);                                      \
            cp_async16(d, x + (size_t)use * 64 + c * 4);                      \
        }                                                                     \
    } while (0)

        // Prologue: 3 committed groups (g0 includes W+bias).
        LOAD_HALF(0, 0);
        cp_commit();                       // g0
        if (1 < L) LOAD_HALF(1, 1);
        cp_commit();                       // g1 (maybe empty)
        if (2 < L) LOAD_HALF(2, 2);
        cp_commit();                       // g2 (maybe empty)

        const int warp = tid >> 5;
        const int lane = tid & 31;
        const int wm = warp >> 2;            // 0..1
        const int wn = warp & 3;             // 0..3
        const int g  = lane >> 2, tg = lane & 3;
        const int lr0 = wm * 16 + g;         // row within 32-row half
        const int sw = (g & 1) << 2;         // XOR swizzle

        for (int i = 0; i < L; i++) {
            const int s    = i & 3;
            const int lt   = i >> 1;
            const int hoff = (i & 1) * 32;

            cp_wait<2>();      // half-stage i's group complete
            __syncthreads();

            const uint4* A0 = (const uint4*)(As + s * 2048 + lr0 * 64);
            const uint4* A1 = (const uint4*)(As + s * 2048 + (lr0 + 8) * 64);
            const uint4* B0 = (const uint4*)(Ws + (wn * 16 + g) * 64);

            float acc[2][4];
#pragma unroll
            for (int nc = 0; nc < 2; nc++) {
                acc[nc][0] = 0.f; acc[nc][1] = 0.f;
                acc[nc][2] = 0.f; acc[nc][3] = 0.f;
            }

#pragma unroll
            for (int j = 0; j < 4; j++) {
                const int cidx = (4 * j + tg) ^ sw;
                uint4 ar0 = A0[cidx];
                uint4 ar1 = A1[cidx];
#pragma unroll
                for (int nc = 0; nc < 2; nc++) {
                    uint4 b4 = B0[nc * 128 + cidx];
                    mma_tf32(acc[nc], ar0.x, ar1.x, ar0.z, ar1.z, b4.x, b4.z);
                    mma_tf32(acc[nc], ar0.y, ar1.y, ar0.w, ar1.w, b4.y, b4.w);
                }
            }

            const int row0 = idx_all[lt * 64 + hoff + lr0];
            const int row1 = idx_all[lt * 64 + hoff + lr0 + 8];
#pragma unroll
            for (int nc = 0; nc < 2; nc++) {
                int col = wn * 16 + nc * 8 + tg * 2;
                float bv0 = bsm[col], bv1 = bsm[col + 1];
                if (row0 >= 0) {
                    float2 v = make_float2(acc[nc][0] + bv0, acc[nc][1] + bv1);
                    *reinterpret_cast<float2*>(out + (size_t)row0 * 64 + col) = v;
                }
                if (row1 >= 0) {
                    float2 v = make_float2(acc[nc][2] + bv0, acc[nc][3] + bv1);
                    *reinterpret_cast<float2*>(out + (size_t)row1 * 64 + col) = v;
                }
            }
            __syncthreads();   // all warps done with stage s

            if (i + 3 < L) LOAD_HALF((i + 3) & 3, i + 3);
            cp_commit();       // exactly one group per iteration
        }
#undef LOAD_HALF
    }

    // --- replay-safe counter reset: last finisher of this type zeroes ---
    __syncthreads();
    if (tid == 0) {
        if (atomicAdd(&g_done[type], 1) == (int)gridDim.x - 1) {
            g_count[type] = 0;
            g_done[type]  = 0;
        }
    }
}

// ---------------------------------------------------------------------------
extern "C" void kernel_launch(void* const* d_in, const int* in_sizes, int n_in,
                              void* d_out, int out_size) {
    const float* x      = (const float*)d_in[0];
    const void*  types  = d_in[1];
    const float* matrix = (const float*)d_in[2];
    const float* bias   = (const float*)d_in[3];
    float*       out    = (float*)d_out;
    const int n = in_sizes[1];

    cudaFuncSetAttribute(k_gemm, cudaFuncAttributeMaxDynamicSharedMemorySize,
                         DSMEM_BYTES);

    k_sort<<<NB, 256>>>(types, matrix, n);

    // Programmatic dependent launch: k_gemm setup overlaps k_sort.
    cudaLaunchConfig_t cfg = {};
    cfg.gridDim  = dim3(SLOTS, NUM_TYPES, 1);
    cfg.blockDim = dim3(256, 1, 1);
    cfg.dynamicSmemBytes = DSMEM_BYTES;
    cfg.stream = 0;
    cudaLaunchAttribute attrs[1];
    attrs[0].id = cudaLaunchAttributeProgrammaticStreamSerialization;
    attrs[0].val.programmaticStreamSerializationAllowed = 1;
    cfg.attrs = attrs;
    cfg.numAttrs = 1;
    cudaLaunchKernelEx(&cfg, k_gemm, x, bias, out);
}